// round 16
// baseline (speedup 1.0000x reference)
#include <cuda_runtime.h>

// Problem constants (fixed shapes from reference)
#define BATCH 8
#define TLEN  4096
#define BC    256
#define RC    64
#define NB0   4
#define NB1   3
#define TB    7           // NB0 + NB1
#define CH0   1024        // x0 channels
#define CH1   768         // x1 channels
#define ROWS_PER_B (CH0 + CH1)   // 1792

// Device-global scratch (allocation-free per harness rules)
__device__ float g_gap[BATCH * BC];
__device__ float g_scores[TB * BATCH * BC];   // [k][b][c], raw scores

// 32-byte evict_last load (sm_103 ptxas requires v8.b32/v4.b64 for this hint).
// Per-batch gap loads all use this: batch slice is only 29.4MB, so it stays
// resident until the same batch's scale pass re-reads it from L2.
__device__ __forceinline__ float ld_evict_last32_sum(const float* p) {
    unsigned long long r0, r1, r2, r3;
    asm volatile("ld.global.nc.L2::evict_last.v4.b64 {%0,%1,%2,%3}, [%4];"
                 : "=l"(r0), "=l"(r1), "=l"(r2), "=l"(r3) : "l"(p));
    float2 a = *reinterpret_cast<float2*>(&r0);
    float2 b = *reinterpret_cast<float2*>(&r1);
    float2 c = *reinterpret_cast<float2*>(&r2);
    float2 d = *reinterpret_cast<float2*>(&r3);
    return ((a.x + a.y) + (b.x + b.y)) + ((c.x + c.y) + (d.x + d.y));
}

// ---------------------------------------------------------------------------
// Per-batch GAP: grid = 256 CTAs (one per c), 256 threads. Reads batch b's
// 29.4MB slice with evict_last (pins it in L2 for this batch's scale pass).
// No dependency wait (x is input-only); triggers completion at end.
// ---------------------------------------------------------------------------
__global__ void __launch_bounds__(256, 8) gap_b_kernel(const float* __restrict__ x0,
                                                       const float* __restrict__ x1,
                                                       int b) {
    const int c = blockIdx.x;           // 0..255
    const int tid = threadIdx.x;

    float acc = 0.0f;
    #pragma unroll
    for (int blk = 0; blk < NB0; ++blk) {
        const float* row = x0 + ((size_t)b * CH0 + (size_t)blk * BC + c) * TLEN;
        #pragma unroll
        for (int i = 0; i < 2; ++i)
            acc += ld_evict_last32_sum(row + (tid + i * 256) * 8);
    }
    #pragma unroll
    for (int blk = 0; blk < NB1; ++blk) {
        const float* row = x1 + ((size_t)b * CH1 + (size_t)blk * BC + c) * TLEN;
        #pragma unroll
        for (int i = 0; i < 2; ++i)
            acc += ld_evict_last32_sum(row + (tid + i * 256) * 8);
    }

    // Block reduction
    __shared__ float warpsum[8];
    #pragma unroll
    for (int o = 16; o > 0; o >>= 1)
        acc += __shfl_down_sync(0xffffffffu, acc, o);
    if ((tid & 31) == 0) warpsum[tid >> 5] = acc;
    __syncthreads();
    if (tid < 8) {
        float v = warpsum[tid];
        #pragma unroll
        for (int o = 4; o > 0; o >>= 1)
            v += __shfl_down_sync(0x000000ffu, v, o);
        if (tid == 0) g_gap[b * BC + c] = v * (1.0f / (float)TLEN);
    }
    __syncthreads();
    cudaTriggerProgrammaticLaunchCompletion();
}

// ---------------------------------------------------------------------------
// Per-batch scores: grid = TB (7) CTAs x 256 threads, k = blockIdx.x.
// PDL on gap_b. Weights are gap-independent: prefetch pre-sync (only costs
// anything on b=0; afterwards they're L2-hot in the evict-normal class).
// ---------------------------------------------------------------------------
__global__ void __launch_bounds__(256) score_b_kernel(const float* __restrict__ W1,
                                                      const float* __restrict__ b1,
                                                      const float* __restrict__ gamma,
                                                      const float* __restrict__ beta,
                                                      const float* __restrict__ Wh,
                                                      const float* __restrict__ bh,
                                                      int b) {
    const int k = blockIdx.x;            // 0..6
    const int tid = threadIdx.x;

    __shared__ float part[4][RC];        // split-K partials
    __shared__ float h_s[RC];

    // --- pre-sync L2 prefetch of everything gap-independent ---
    {
        const char* whk = (const char*)(Wh + (size_t)k * RC * BC); // 64KB slice
        #pragma unroll
        for (int i = 0; i < 2; ++i)
            asm volatile("prefetch.global.L2 [%0];" :: "l"(whk + (tid + i * 256) * 128));
        const char* w1p = (const char*)W1;                          // 64KB
        #pragma unroll
        for (int i = 0; i < 2; ++i)
            asm volatile("prefetch.global.L2 [%0];" :: "l"(w1p + (tid + i * 256) * 128));
        if (tid < 8)
            asm volatile("prefetch.global.L2 [%0];" :: "l"((const char*)(bh + k * BC) + tid * 128));
    }

    cudaGridDependencySynchronize();     // wait for gap_b's g_gap writes

    // --- h[b] split-K: thread (s, r) accumulates over c in [s*64, s*64+64)
    {
        const int s = tid >> 6;          // 0..3
        const int r = tid & (RC - 1);    // 0..63
        const float* gp = &g_gap[b * BC + s * 64];
        const float* wp = W1 + (size_t)(s * 64) * RC + r;
        float acc = 0.0f;
        #pragma unroll 16
        for (int i = 0; i < 64; ++i)
            acc = fmaf(gp[i], wp[(size_t)i * RC], acc);   // coalesced: r varies
        part[s][r] = acc;
    }
    __syncthreads();
    if (tid < RC) {
        const int r = tid;
        float s = part[0][r] + part[1][r] + part[2][r] + part[3][r] + b1[r];
        const float bnscale = gamma[r] * rsqrtf(1.0f + 1e-5f);
        h_s[r] = fmaxf(fmaf(s, bnscale, beta[r]), 0.0f);
    }
    __syncthreads();

    // --- score[k][b][c], c = tid; Wh reads coalesced across c ---
    const int c = tid;
    float s = bh[k * BC + c];
    const float* w = Wh + (size_t)k * RC * BC + c;
    #pragma unroll 16
    for (int r = 0; r < RC; ++r)
        s = fmaf(h_s[r], w[(size_t)r * BC], s);
    g_scores[(k * BATCH + b) * BC + c] = s;

    cudaTriggerProgrammaticLaunchCompletion();
}

// ---------------------------------------------------------------------------
// Per-batch scale: grid = 1792 CTAs x 128 threads (single wave at >=13
// CTAs/SM), one channel-row (16KB) per CTA. Triggers EARLY (before its own
// dependency sync) so gap_{b+1} starts while this batch's scale drains.
// Loads are evict-first (the hits come from the batch's pinned L2 lines and
// demote on hit); stores are evict-first.
// ---------------------------------------------------------------------------
__global__ void __launch_bounds__(128, 13) scale_b_kernel(const float* __restrict__ x0,
                                                          const float* __restrict__ x1,
                                                          float* __restrict__ out,
                                                          int b) {
    const int row = blockIdx.x;          // 0..1791
    const int tid = threadIdx.x;

    const float* src;
    float* dst;
    int kblk, c;
    if (row < CH0) {
        src = x0 + ((size_t)b * CH0 + row) * TLEN;
        dst = out + ((size_t)b * CH0 + row) * TLEN;
        kblk = row >> 8;
        c = row & (BC - 1);
    } else {
        const int r1 = row - CH0;
        src = x1 + ((size_t)b * CH1 + r1) * TLEN;
        dst = out + (size_t)BATCH * CH0 * TLEN + ((size_t)b * CH1 + r1) * TLEN;
        kblk = NB0 + (r1 >> 8);
        c = r1 & (BC - 1);
    }

    const float4* s4 = reinterpret_cast<const float4*>(src);
    float4* d4 = reinterpret_cast<float4*>(dst);

    // Pre-sync: issue first half of the row's loads (independent of scores).
    float4 v[4];
    #pragma unroll
    for (int i = 0; i < 4; ++i)
        v[i] = __ldcs(s4 + tid + i * 128);

    // Early trigger: gap_{b+1} has no data dependency on this kernel.
    cudaTriggerProgrammaticLaunchCompletion();
    cudaGridDependencySynchronize();     // wait for score_b's g_scores

    __shared__ float a_s;
    if (tid == 0) {
        float sc[TB];
        float mx = -1e30f;
        #pragma unroll
        for (int k = 0; k < TB; ++k) {
            sc[k] = __ldg(&g_scores[(k * BATCH + b) * BC + c]);
            mx = fmaxf(mx, sc[k]);
        }
        float sum = 0.0f;
        #pragma unroll
        for (int k = 0; k < TB; ++k) sum += __expf(sc[k] - mx);
        a_s = __expf(sc[kblk] - mx) / sum;
    }
    __syncthreads();
    const float a = a_s;

    #pragma unroll
    for (int i = 0; i < 4; ++i) {
        v[i].x *= a; v[i].y *= a; v[i].z *= a; v[i].w *= a;
        __stcs(d4 + tid + i * 128, v[i]);
    }
    // Second half: load, scale, store (post-sync streaming).
    #pragma unroll
    for (int i = 4; i < 8; ++i) {
        float4 u = __ldcs(s4 + tid + i * 128);
        u.x *= a; u.y *= a; u.z *= a; u.w *= a;
        __stcs(d4 + tid + i * 128, u);
    }
}

// ---------------------------------------------------------------------------
static inline void launch_pdl(void* fn, dim3 grid, dim3 block, void** args) {
    cudaLaunchConfig_t cfg = {};
    cfg.gridDim = grid;
    cfg.blockDim = block;
    cudaLaunchAttribute attr[1];
    attr[0].id = cudaLaunchAttributeProgrammaticStreamSerialization;
    attr[0].val.programmaticStreamSerializationAllowed = 1;
    cfg.attrs = attr;
    cfg.numAttrs = 1;
    cudaLaunchKernelExC(&cfg, fn, args);
}

extern "C" void kernel_launch(void* const* d_in, const int* in_sizes, int n_in,
                              void* d_out, int out_size) {
    const float* x0    = (const float*)d_in[0];  // [8,1024,4096]
    const float* x1    = (const float*)d_in[1];  // [8,768,4096]
    const float* W1    = (const float*)d_in[2];  // [256,64]
    const float* b1    = (const float*)d_in[3];  // [64]
    const float* gamma = (const float*)d_in[4];  // [64]
    const float* beta  = (const float*)d_in[5];  // [64]
    const float* Wh    = (const float*)d_in[6];  // [7,64,256]
    const float* bh    = (const float*)d_in[7];  // [7,256]
    float* out = (float*)d_out;

    for (int b = 0; b < BATCH; ++b) {
        {   // gap_b — PDL on previous scale (no data dep; overlaps it)
            void* args[] = {(void*)&x0, (void*)&x1, (void*)&b};
            if (b == 0) {
                gap_b_kernel<<<BC, 256>>>(x0, x1, 0);
            } else {
                launch_pdl((void*)gap_b_kernel, dim3(BC), dim3(256), args);
            }
        }
        {   // score_b — PDL on gap_b
            void* args[] = {(void*)&W1, (void*)&b1, (void*)&gamma, (void*)&beta,
                            (void*)&Wh, (void*)&bh, (void*)&b};
            launch_pdl((void*)score_b_kernel, dim3(TB), dim3(256), args);
        }
        {   // scale_b — PDL on score_b
            void* args[] = {(void*)&x0, (void*)&x1, (void*)&out, (void*)&b};
            launch_pdl((void*)scale_b_kernel, dim3(ROWS_PER_B), dim3(128), args);
        }
    }
}

// round 17
// speedup vs baseline: 1.6362x; 1.6362x over previous
#include <cuda_runtime.h>

// Problem constants (fixed shapes from reference)
#define BATCH 8
#define TLEN  4096
#define BC    256
#define RC    64
#define NB0   4
#define NB1   3
#define TB    7           // NB0 + NB1
#define CH0   1024        // x0 channels
#define CH1   768         // x1 channels
#define ROWS_PER_B (CH0 + CH1)   // 1792
#define HB    4           // batches per half
#define HALF_ROWS (HB * ROWS_PER_B)   // 7168

// Device-global scratch (allocation-free per harness rules)
__device__ float g_gap[BATCH * BC];
__device__ float g_scores[TB * BATCH * BC];   // [k][b][c], raw scores

// 32-byte evict_last load (sm_103 ptxas requires v8.b32/v4.b64 for this hint).
// Each half's 112MB slice is pinned evict_last so the same half's scale pass
// re-reads it from L2.
__device__ __forceinline__ float ld_evict_last32_sum(const float* p) {
    unsigned long long r0, r1, r2, r3;
    asm volatile("ld.global.nc.L2::evict_last.v4.b64 {%0,%1,%2,%3}, [%4];"
                 : "=l"(r0), "=l"(r1), "=l"(r2), "=l"(r3) : "l"(p));
    float2 a = *reinterpret_cast<float2*>(&r0);
    float2 b = *reinterpret_cast<float2*>(&r1);
    float2 c = *reinterpret_cast<float2*>(&r2);
    float2 d = *reinterpret_cast<float2*>(&r3);
    return ((a.x + a.y) + (b.x + b.y)) + ((c.x + c.y) + (d.x + d.y));
}

// ---------------------------------------------------------------------------
// Per-half GAP: grid = HB*BC = 1024 CTAs (near-full wave -> saturated DRAM),
// 256 threads. Reads the half's 112MB slice with evict_last.
// ---------------------------------------------------------------------------
__global__ void __launch_bounds__(256, 8) gap_h_kernel(const float* __restrict__ x0,
                                                       const float* __restrict__ x1,
                                                       int half) {
    const int brel = blockIdx.x >> 8;    // 0..3
    const int c = blockIdx.x & (BC - 1);
    const int b = half * HB + brel;
    const int tid = threadIdx.x;

    float acc = 0.0f;
    #pragma unroll
    for (int blk = 0; blk < NB0; ++blk) {
        const float* row = x0 + ((size_t)b * CH0 + (size_t)blk * BC + c) * TLEN;
        #pragma unroll
        for (int i = 0; i < 2; ++i)
            acc += ld_evict_last32_sum(row + (tid + i * 256) * 8);
    }
    #pragma unroll
    for (int blk = 0; blk < NB1; ++blk) {
        const float* row = x1 + ((size_t)b * CH1 + (size_t)blk * BC + c) * TLEN;
        #pragma unroll
        for (int i = 0; i < 2; ++i)
            acc += ld_evict_last32_sum(row + (tid + i * 256) * 8);
    }

    // Block reduction
    __shared__ float warpsum[8];
    #pragma unroll
    for (int o = 16; o > 0; o >>= 1)
        acc += __shfl_down_sync(0xffffffffu, acc, o);
    if ((tid & 31) == 0) warpsum[tid >> 5] = acc;
    __syncthreads();
    if (tid < 8) {
        float v = warpsum[tid];
        #pragma unroll
        for (int o = 4; o > 0; o >>= 1)
            v += __shfl_down_sync(0x000000ffu, v, o);
        if (tid == 0) g_gap[b * BC + c] = v * (1.0f / (float)TLEN);
    }
    __syncthreads();
    cudaTriggerProgrammaticLaunchCompletion();
}

// ---------------------------------------------------------------------------
// Per-half scores: grid = TB*HB = 28 CTAs x 256 threads.
// PDL on gap_h. Weight prefetch pre-sync (hot after the first half).
// ---------------------------------------------------------------------------
__global__ void __launch_bounds__(256) score_h_kernel(const float* __restrict__ W1,
                                                      const float* __restrict__ b1,
                                                      const float* __restrict__ gamma,
                                                      const float* __restrict__ beta,
                                                      const float* __restrict__ Wh,
                                                      const float* __restrict__ bh,
                                                      int half) {
    const int k = blockIdx.x >> 2;       // 0..6
    const int brel = blockIdx.x & 3;     // 0..3
    const int b = half * HB + brel;
    const int tid = threadIdx.x;

    __shared__ float part[4][RC];        // split-K partials
    __shared__ float h_s[RC];

    // --- pre-sync L2 prefetch of everything gap-independent ---
    {
        const char* whk = (const char*)(Wh + (size_t)k * RC * BC); // 64KB slice
        #pragma unroll
        for (int i = 0; i < 2; ++i)
            asm volatile("prefetch.global.L2 [%0];" :: "l"(whk + (tid + i * 256) * 128));
        const char* w1p = (const char*)W1;                          // 64KB
        #pragma unroll
        for (int i = 0; i < 2; ++i)
            asm volatile("prefetch.global.L2 [%0];" :: "l"(w1p + (tid + i * 256) * 128));
        if (tid < 8)
            asm volatile("prefetch.global.L2 [%0];" :: "l"((const char*)(bh + k * BC) + tid * 128));
    }

    cudaGridDependencySynchronize();     // wait for gap_h's g_gap writes

    // --- h[b] split-K: thread (s, r) accumulates over c in [s*64, s*64+64)
    {
        const int s = tid >> 6;          // 0..3
        const int r = tid & (RC - 1);    // 0..63
        const float* gp = &g_gap[b * BC + s * 64];
        const float* wp = W1 + (size_t)(s * 64) * RC + r;
        float acc = 0.0f;
        #pragma unroll 16
        for (int i = 0; i < 64; ++i)
            acc = fmaf(gp[i], wp[(size_t)i * RC], acc);   // coalesced: r varies
        part[s][r] = acc;
    }
    __syncthreads();
    if (tid < RC) {
        const int r = tid;
        float s = part[0][r] + part[1][r] + part[2][r] + part[3][r] + b1[r];
        const float bnscale = gamma[r] * rsqrtf(1.0f + 1e-5f);
        h_s[r] = fmaxf(fmaf(s, bnscale, beta[r]), 0.0f);
    }
    __syncthreads();

    // --- score[k][b][c], c = tid; Wh reads coalesced across c ---
    const int c = tid;
    float s = bh[k * BC + c];
    const float* w = Wh + (size_t)k * RC * BC + c;
    #pragma unroll 16
    for (int r = 0; r < RC; ++r)
        s = fmaf(h_s[r], w[(size_t)r * BC], s);
    g_scores[(k * BATCH + b) * BC + c] = s;

    cudaTriggerProgrammaticLaunchCompletion();
}

// ---------------------------------------------------------------------------
// Per-half scale: grid = 7168 CTAs x 128 threads, one channel-row (16KB) per
// CTA. Triggers EARLY so gap of the next half overlaps this half's drain.
// Loads/stores evict-first; the half's pinned lines provide L2 hits.
// ---------------------------------------------------------------------------
__global__ void __launch_bounds__(128) scale_h_kernel(const float* __restrict__ x0,
                                                      const float* __restrict__ x1,
                                                      float* __restrict__ out,
                                                      int half) {
    const int q = blockIdx.x;            // 0..7167
    const int brel = q / ROWS_PER_B;     // 0..3
    const int row = q - brel * ROWS_PER_B;
    const int b = half * HB + brel;
    const int tid = threadIdx.x;

    const float* src;
    float* dst;
    int kblk, c;
    if (row < CH0) {
        src = x0 + ((size_t)b * CH0 + row) * TLEN;
        dst = out + ((size_t)b * CH0 + row) * TLEN;
        kblk = row >> 8;
        c = row & (BC - 1);
    } else {
        const int r1 = row - CH0;
        src = x1 + ((size_t)b * CH1 + r1) * TLEN;
        dst = out + (size_t)BATCH * CH0 * TLEN + ((size_t)b * CH1 + r1) * TLEN;
        kblk = NB0 + (r1 >> 8);
        c = r1 & (BC - 1);
    }

    const float4* s4 = reinterpret_cast<const float4*>(src);
    float4* d4 = reinterpret_cast<float4*>(dst);

    // Pre-sync: issue first half of the row's loads (independent of scores).
    float4 v[4];
    #pragma unroll
    for (int i = 0; i < 4; ++i)
        v[i] = __ldcs(s4 + tid + i * 128);

    // Early trigger: the next half's gap has no data dependency on us.
    cudaTriggerProgrammaticLaunchCompletion();
    cudaGridDependencySynchronize();     // wait for score_h's g_scores

    __shared__ float a_s;
    if (tid == 0) {
        float sc[TB];
        float mx = -1e30f;
        #pragma unroll
        for (int k = 0; k < TB; ++k) {
            sc[k] = __ldg(&g_scores[(k * BATCH + b) * BC + c]);
            mx = fmaxf(mx, sc[k]);
        }
        float sum = 0.0f;
        #pragma unroll
        for (int k = 0; k < TB; ++k) sum += __expf(sc[k] - mx);
        a_s = __expf(sc[kblk] - mx) / sum;
    }
    __syncthreads();
    const float a = a_s;

    #pragma unroll
    for (int i = 0; i < 4; ++i) {
        v[i].x *= a; v[i].y *= a; v[i].z *= a; v[i].w *= a;
        __stcs(d4 + tid + i * 128, v[i]);
    }
    #pragma unroll
    for (int i = 4; i < 8; ++i) {
        float4 u = __ldcs(s4 + tid + i * 128);
        u.x *= a; u.y *= a; u.z *= a; u.w *= a;
        __stcs(d4 + tid + i * 128, u);
    }
}

// ---------------------------------------------------------------------------
static inline void launch_pdl(void* fn, dim3 grid, dim3 block, void** args) {
    cudaLaunchConfig_t cfg = {};
    cfg.gridDim = grid;
    cfg.blockDim = block;
    cudaLaunchAttribute attr[1];
    attr[0].id = cudaLaunchAttributeProgrammaticStreamSerialization;
    attr[0].val.programmaticStreamSerializationAllowed = 1;
    cfg.attrs = attr;
    cfg.numAttrs = 1;
    cudaLaunchKernelExC(&cfg, fn, args);
}

extern "C" void kernel_launch(void* const* d_in, const int* in_sizes, int n_in,
                              void* d_out, int out_size) {
    const float* x0    = (const float*)d_in[0];  // [8,1024,4096]
    const float* x1    = (const float*)d_in[1];  // [8,768,4096]
    const float* W1    = (const float*)d_in[2];  // [256,64]
    const float* b1    = (const float*)d_in[3];  // [64]
    const float* gamma = (const float*)d_in[4];  // [64]
    const float* beta  = (const float*)d_in[5];  // [64]
    const float* Wh    = (const float*)d_in[6];  // [7,64,256]
    const float* bh    = (const float*)d_in[7];  // [7,256]
    float* out = (float*)d_out;

    for (int half = 0; half < 2; ++half) {
        {   // gap_h — plain for half 0; PDL on previous scale's early trigger
            void* args[] = {(void*)&x0, (void*)&x1, (void*)&half};
            if (half == 0) {
                gap_h_kernel<<<HB * BC, 256>>>(x0, x1, 0);
            } else {
                launch_pdl((void*)gap_h_kernel, dim3(HB * BC), dim3(256), args);
            }
        }
        {   // score_h — PDL on gap_h
            void* args[] = {(void*)&W1, (void*)&b1, (void*)&gamma, (void*)&beta,
                            (void*)&Wh, (void*)&bh, (void*)&half};
            launch_pdl((void*)score_h_kernel, dim3(TB * HB), dim3(256), args);
        }
        {   // scale_h — PDL on score_h
            void* args[] = {(void*)&x0, (void*)&x1, (void*)&out, (void*)&half};
            launch_pdl((void*)scale_h_kernel, dim3(HALF_ROWS), dim3(128), args);
        }
    }
}